// round 6
// baseline (speedup 1.0000x reference)
#include <cuda_runtime.h>

// Problem constants (fixed by the dataset)
#define B   4
#define P   12000
#define NF  64
#define XS  512
#define YS  512
#define CELLS    (XS * YS)                // 262144 per batch
#define BP_TOTAL (B * P)                  // 48000
#define PF 6                              // prefetched fixup tasks per warp

// Slot map: 0 = empty, bp+1 = chain head. Zero-initialized by CUDA at load,
// and SELF-CLEANED by fused_kernel each call -> no init kernel needed and
// every graph replay starts from a valid empty map.
__device__ int g_slot[B * CELLS];         // 4 MB
__device__ int g_next[BP_TOTAL];          // -1 terminated chains (written before read)

// ---------------------------------------------------------------------------
// Kernel A: build per-cell pillar chains. One atomicExch per valid pillar.
// prev==0 (empty) maps to terminator -1 via prev-1.
// ---------------------------------------------------------------------------
__global__ void claim_kernel(const int* __restrict__ coord,
                             const int* __restrict__ contains) {
    unsigned int bp = blockIdx.x * blockDim.x + threadIdx.x;
    if (bp >= BP_TOTAL) return;
    if (contains[bp] != 1) return;
    int b = bp / P;
    int y = coord[bp * 3 + 1];
    int x = coord[bp * 3 + 2];
    int idx = b * CELLS + y * XS + x;
    int prev = atomicExch(&g_slot[idx], (int)bp + 1);
    g_next[bp] = prev - 1;
}

// ---------------------------------------------------------------------------
// Kernel B: fused zero + overwrite, barrier-free, self-cleaning.
// Block = (batch, 128-quad tile), 128 threads (4 warps). Thread owns 1 quad
// across all 64 planes.
//   1: load quad's int4 slot entry, store zeros back (self-clean).
//   2: warp-compact touched cells (ballot+popc) into smem task lists.
//   3: PREFETCH up to PF tasks: head pillar row (lane=f, coalesced 128B x2)
//      + g_next, into registers.
//   4: unconditional zero stream: 64 strided STG.128 (hides the prefetch).
//   5: __syncwarp, consume prefetched fixups (chain remainder rare),
//      2 stores per lane per cell onto lines this warp just wrote (L2-hit).
// ---------------------------------------------------------------------------
__global__ void fused_kernel(const float* __restrict__ pillars,
                             float* __restrict__ out) {
    __shared__ int s_cell[4][128];
    __shared__ int s_head[4][128];

    const unsigned tid  = threadIdx.x;          // 0..127
    const unsigned lane = tid & 31;
    const unsigned w    = tid >> 5;             // warp in block
    const unsigned blk  = blockIdx.x;           // 0..2047
    const unsigned b    = blk >> 9;             // batch
    const unsigned tile = blk & 511;            // 512 tiles per batch
    const unsigned q    = (tile << 7) + tid;    // quad within batch [0,65536)

    // 1: slot read + self-clean
    int4 s4 = ((const int4*)g_slot)[(b << 16) + q];
    ((int4*)g_slot)[(b << 16) + q] = make_int4(0, 0, 0, 0);
    int sl[4] = {s4.x, s4.y, s4.z, s4.w};

    // 2: warp-level compaction (no atomics, no block barrier)
    unsigned n = 0;
    #pragma unroll
    for (int k = 0; k < 4; ++k) {
        unsigned m = __ballot_sync(0xFFFFFFFFu, sl[k] > 0);
        if (sl[k] > 0) {
            unsigned pos = n + __popc(m & ((1u << lane) - 1));
            s_cell[w][pos] = (int)((q << 2) + k);
            s_head[w][pos] = sl[k] - 1;
        }
        n += __popc(m);
    }
    __syncwarp();

    // 3: prefetch fixup data (loads retire underneath the store stream)
    float v0[PF], v1[PF];
    int   nx[PF];
    #pragma unroll
    for (int i = 0; i < PF; ++i) {
        if (i < (int)n) {
            unsigned h = (unsigned)s_head[w][i];
            v0[i] = pillars[h * NF + lane];
            v1[i] = pillars[h * NF + 32 + lane];
            nx[i] = g_next[h];
        }
    }

    // 4: unconditional zero stream, all 64 planes
    float4* base = (float4*)out + ((b * NF) << 16) + q;
    const float4 z = make_float4(0.f, 0.f, 0.f, 0.f);
    #pragma unroll
    for (unsigned j = 0; j < NF; ++j)
        base[j << 16] = z;

    __syncwarp();   // order zero-stores across the warp before fixups

    // 5a: consume prefetched fixups
    #pragma unroll
    for (int i = 0; i < PF; ++i) {
        if (i < (int)n) {
            float a0 = v0[i], a1 = v1[i];
            int p = nx[i];
            while (p >= 0) {                     // rare collision chains
                a0 += pillars[(unsigned)p * NF + lane];
                a1 += pillars[(unsigned)p * NF + 32 + lane];
                p = g_next[p];
            }
            unsigned cell = (unsigned)s_cell[w][i];
            out[((b * NF + lane)      << 18) + cell] = a0;
            out[((b * NF + 32 + lane) << 18) + cell] = a1;
        }
    }
    // 5b: overflow tasks (>PF touched cells in this warp, ~3% of warps)
    for (unsigned i = PF; i < n; ++i) {
        unsigned h = (unsigned)s_head[w][i];
        float a0 = pillars[h * NF + lane];
        float a1 = pillars[h * NF + 32 + lane];
        int p = g_next[h];
        while (p >= 0) {
            a0 += pillars[(unsigned)p * NF + lane];
            a1 += pillars[(unsigned)p * NF + 32 + lane];
            p = g_next[p];
        }
        unsigned cell = (unsigned)s_cell[w][i];
        out[((b * NF + lane)      << 18) + cell] = a0;
        out[((b * NF + 32 + lane) << 18) + cell] = a1;
    }
}

extern "C" void kernel_launch(void* const* d_in, const int* in_sizes, int n_in,
                              void* d_out, int out_size) {
    const float* pillars  = (const float*)d_in[0];  // [B, P, NF] fp32
    const int*   coord    = (const int*)  d_in[1];  // [B, P, 3]  int32
    const int*   contains = (const int*)  d_in[2];  // [B, P]     int32
    float*       out      = (float*)d_out;          // [B, NF, XS, YS] fp32

    {   // A: build chains (48000 threads)
        const int threads = 256;
        claim_kernel<<<(BP_TOTAL + threads - 1) / threads, threads>>>(coord, contains);
    }
    {   // B: fused zero + overwrite + self-clean (2048 blocks x 128 threads)
        fused_kernel<<<2048, 128>>>(pillars, out);
    }
}

// round 7
// speedup vs baseline: 1.1000x; 1.1000x over previous
#include <cuda_runtime.h>

// Problem constants (fixed by the dataset)
#define B   4
#define P   12000
#define NF  64
#define XS  512
#define YS  512
#define CELLS    (XS * YS)                // 262144 per batch
#define BP_TOTAL (B * P)                  // 48000
#define SPANS    256                      // 1024-cell spans per batch
#define LIST_MAX 128                      // >> mean 23.4 touched/span (21 sigma)

// Epoch-tagged slot map: value = (epoch<<17) | (bp+1); epoch in [1,32767].
// Entries written in a previous call parse as empty -> no 4 MB init needed.
__device__ unsigned g_epoch;                      // current tag (0 at load)
__device__ unsigned g_slot[B * CELLS];            // 4 MB
__device__ int      g_next[BP_TOTAL];             // chain next, -1 terminated
__device__ unsigned g_cnt[B * SPANS];             // touched cells per span
__device__ int      g_list[B * SPANS * LIST_MAX]; // touched cell ids (512 KB)

// ---------------------------------------------------------------------------
// K0: bump epoch + clear span counters. One block.
// ---------------------------------------------------------------------------
__global__ void reset_kernel() {
    if (threadIdx.x == 0) g_epoch = g_epoch % 32767u + 1u;  // 1..32767, never 0
    g_cnt[threadIdx.x] = 0;                                  // 1024 counters
}

// ---------------------------------------------------------------------------
// K1: build per-cell chains + per-span touched lists.
// First claimant of a cell (this epoch) registers the cell in its span list.
// ---------------------------------------------------------------------------
__global__ void claim_kernel(const int* __restrict__ coord,
                             const int* __restrict__ contains) {
    unsigned bp = blockIdx.x * blockDim.x + threadIdx.x;
    if (bp >= BP_TOTAL) return;
    if (contains[bp] != 1) return;

    const unsigned e = g_epoch;                  // uniform L2 load
    const unsigned b = bp / P;
    const int y = coord[bp * 3 + 1];
    const int x = coord[bp * 3 + 2];
    const unsigned cell = (unsigned)(y * XS + x);

    unsigned old = atomicExch(&g_slot[b * CELLS + cell], (e << 17) | (bp + 1u));
    bool fresh = (old >> 17) == e;               // cell already claimed this call?
    g_next[bp] = fresh ? (int)(old & 0x1FFFFu) - 1 : -1;

    if (!fresh) {                                // first claimant: register cell
        unsigned span = b * SPANS + (cell >> 10);
        unsigned pos = atomicAdd(&g_cnt[span], 1u);
        if (pos < LIST_MAX)
            g_list[span * LIST_MAX + pos] = (int)cell;
    }
}

// ---------------------------------------------------------------------------
// K2: zero + fixup with the proven linear geometry.
// Block = one 4 KB chunk: blk -> (b, f, span), span fastest => block id order
// equals address order (globally linear sweep, 37 waves, exactly round-1).
//   - load span count + this thread's list entry up front (hidden by store)
//   - one linear float4 zero store per thread
//   - __syncthreads, then ~23 threads resolve their cell: slot head ->
//     chain walk over pillars[p*64+f] -> 4B overwrite on a just-written line.
// ---------------------------------------------------------------------------
__global__ void fused_kernel(const float* __restrict__ pillars,
                             float* __restrict__ out) {
    const unsigned blk  = blockIdx.x;            // 0..65535
    const unsigned tid  = threadIdx.x;           // 0..255
    const unsigned b    = blk >> 14;
    const unsigned f    = (blk >> 8) & 63;
    const unsigned span = blk & 255;
    const unsigned sp   = b * SPANS + span;

    // Early independent loads (retire under the store stream)
    const unsigned n = g_cnt[sp];                            // broadcast
    int cell = (tid < LIST_MAX) ? g_list[sp * LIST_MAX + tid] : 0;  // prefetch

    // Linear zero store: one float4 per thread, block = contiguous 4 KB
    ((float4*)out)[(blk << 8) + tid] = make_float4(0.f, 0.f, 0.f, 0.f);

    __syncthreads();   // order zero-stores before fixup overwrites (block scope)

    if (tid < n && tid < LIST_MAX) {
        unsigned head = g_slot[b * CELLS + (unsigned)cell];  // fresh this call
        int p = (int)(head & 0x1FFFFu) - 1;
        float acc = 0.f;
        while (p >= 0) {                                     // chain length ~1
            acc += pillars[(unsigned)p * NF + f];
            p = g_next[p];
        }
        out[((b * NF + f) << 18) + (unsigned)cell] = acc;
    }
}

extern "C" void kernel_launch(void* const* d_in, const int* in_sizes, int n_in,
                              void* d_out, int out_size) {
    const float* pillars  = (const float*)d_in[0];  // [B, P, NF] fp32
    const int*   coord    = (const int*)  d_in[1];  // [B, P, 3]  int32
    const int*   contains = (const int*)  d_in[2];  // [B, P]     int32
    float*       out      = (float*)d_out;          // [B, NF, XS, YS] fp32

    reset_kernel<<<1, B * SPANS>>>();                            // 1024 threads
    claim_kernel<<<(BP_TOTAL + 255) / 256, 256>>>(coord, contains);
    fused_kernel<<<B * NF * SPANS, 256>>>(pillars, out);         // 65536 blocks
}